// round 3
// baseline (speedup 1.0000x reference)
#include <cuda_runtime.h>

#define NNODES 100000
#define CDIM   128
#define EDGES  3200000

// Scratch (allocation-free rule: __device__ globals)
__device__ float g_agg[(size_t)NNODES * CDIM];
__device__ float g_h1 [(size_t)NNODES * CDIM];
__device__ float g_h2 [(size_t)NNODES * CDIM];
__device__ float g_inv[NNODES];

// ---------------------------------------------------------------------------
// Degree count: cnt[dst] += 1  (atomicAdd with unused return -> RED)
__global__ void count_kernel(const int* __restrict__ ei, float* __restrict__ cnt) {
    int e = blockIdx.x * blockDim.x + threadIdx.x;
    if (e < EDGES) {
        int dst = ei[EDGES + e];
        atomicAdd(cnt + dst, 1.0f);
    }
}

__global__ void inv_kernel(float* __restrict__ inv) {
    int n = blockIdx.x * blockDim.x + threadIdx.x;
    if (n < NNODES) {
        float c = inv[n];
        inv[n] = 1.0f / fmaxf(c, 1.0f);
    }
}

// ---------------------------------------------------------------------------
// Scatter: one warp per edge. Gather full 128-float row of h[src] (float4 per
// lane, coalesced) and reduce into agg[dst] with red.global.add.v4.f32.
__global__ void scatter_kernel(const int* __restrict__ ei,
                               const float* __restrict__ h,
                               float* __restrict__ agg) {
    long long gtid = (long long)blockIdx.x * blockDim.x + threadIdx.x;
    long long warp = gtid >> 5;
    int lane = threadIdx.x & 31;
    if (warp >= EDGES) return;
    int src = ei[warp];
    int dst = ei[EDGES + warp];
    float4 v = *(const float4*)(h + (size_t)src * CDIM + lane * 4);
    float* dptr = agg + (size_t)dst * CDIM + lane * 4;
    asm volatile("red.global.add.v4.f32 [%0], {%1,%2,%3,%4};"
                 :: "l"(dptr), "f"(v.x), "f"(v.y), "f"(v.z), "f"(v.w)
                 : "memory");
}

// ---------------------------------------------------------------------------
// Fused combine: out[n,c] = act( sum_k agg[n,k]*inv[n]*Wl[c,k]
//                              + sum_k h[n,k]*Wr[c,k] + bl[c] )
// Register-blocked SGEMM over implicit concat (K = 2*CDIM).
// BM=128 nodes, full COUT, BK=16, 256 threads, TM=8 x TN=COUT/16 per thread.
template<int COUT, bool RELU>
__global__ __launch_bounds__(256)
void combine_kernel(const float* __restrict__ agg, const float* __restrict__ h,
                    const float* __restrict__ inv,
                    const float* __restrict__ Wl, const float* __restrict__ bl,
                    const float* __restrict__ Wr, float* __restrict__ out) {
    constexpr int BM = 128, BK = 16;
    constexpr int TM = 8, TN = COUT / 16;

    __shared__ float As[BK][BM];
    __shared__ float Bs[BK][COUT];

    const int tid = threadIdx.x;
    const int m0  = blockIdx.x * BM;
    const int tm  = (tid >> 4) * TM;    // 0..120
    const int tc  = (tid & 15) * TN;    // 0..COUT-TN

    float acc[TM][TN];
#pragma unroll
    for (int i = 0; i < TM; i++)
#pragma unroll
        for (int j = 0; j < TN; j++) acc[i][j] = 0.f;

#pragma unroll
    for (int phase = 0; phase < 2; phase++) {
        const float* Asrc = phase ? h  : agg;
        const float* Bsrc = phase ? Wr : Wl;

        for (int kc = 0; kc < CDIM; kc += BK) {
            __syncthreads();
            // Load A tile (BM x BK), transposed into As[k][m]
#pragma unroll
            for (int s = tid; s < BM * BK / 4; s += 256) {
                int m  = s >> 2;
                int kg = (s & 3) * 4;
                int node = m0 + m;
                float4 v = make_float4(0.f, 0.f, 0.f, 0.f);
                if (node < NNODES) {
                    v = *(const float4*)(Asrc + (size_t)node * CDIM + kc + kg);
                    if (phase == 0) {
                        float iv = inv[node];
                        v.x *= iv; v.y *= iv; v.z *= iv; v.w *= iv;
                    }
                }
                As[kg + 0][m] = v.x; As[kg + 1][m] = v.y;
                As[kg + 2][m] = v.z; As[kg + 3][m] = v.w;
            }
            // Load B tile (COUT x BK), transposed into Bs[k][c]
#pragma unroll
            for (int s = tid; s < COUT * BK / 4; s += 256) {
                int c  = s >> 2;
                int kg = (s & 3) * 4;
                float4 v = *(const float4*)(Bsrc + (size_t)c * CDIM + kc + kg);
                Bs[kg + 0][c] = v.x; Bs[kg + 1][c] = v.y;
                Bs[kg + 2][c] = v.z; Bs[kg + 3][c] = v.w;
            }
            __syncthreads();

#pragma unroll
            for (int k = 0; k < BK; k++) {
                float ra[TM], rb[TN];
#pragma unroll
                for (int i = 0; i < TM; i++) ra[i] = As[k][tm + i];
#pragma unroll
                for (int j = 0; j < TN; j++) rb[j] = Bs[k][tc + j];
#pragma unroll
                for (int i = 0; i < TM; i++)
#pragma unroll
                    for (int j = 0; j < TN; j++)
                        acc[i][j] += ra[i] * rb[j];
            }
        }
    }

    // Epilogue
#pragma unroll
    for (int i = 0; i < TM; i++) {
        int node = m0 + tm + i;
        if (node >= NNODES) continue;
#pragma unroll
        for (int j = 0; j < TN; j++) {
            float v = acc[i][j] + bl[tc + j];
            if (RELU) v = fmaxf(v, 0.f);
            out[(size_t)node * COUT + tc + j] = v;
        }
    }
}

// ---------------------------------------------------------------------------
extern "C" void kernel_launch(void* const* d_in, const int* in_sizes, int n_in,
                              void* d_out, int out_size) {
    const float* x   = (const float*)d_in[0];
    const int*   ei  = (const int*)d_in[1];      // int32! (JAX x64 disabled)
    const float* Wl1 = (const float*)d_in[2];
    const float* bl1 = (const float*)d_in[3];
    const float* Wr1 = (const float*)d_in[4];
    const float* Wl2 = (const float*)d_in[5];
    const float* bl2 = (const float*)d_in[6];
    const float* Wr2 = (const float*)d_in[7];
    const float* Wl3 = (const float*)d_in[8];
    const float* bl3 = (const float*)d_in[9];
    const float* Wr3 = (const float*)d_in[10];
    float* out = (float*)d_out;

    float *agg, *h1, *h2, *inv;
    cudaGetSymbolAddress((void**)&agg, g_agg);
    cudaGetSymbolAddress((void**)&h1,  g_h1);
    cudaGetSymbolAddress((void**)&h2,  g_h2);
    cudaGetSymbolAddress((void**)&inv, g_inv);

    const size_t aggBytes = (size_t)NNODES * CDIM * sizeof(float);
    const int cntBlocks = (EDGES + 255) / 256;
    const long long scatterThreads = (long long)EDGES * 32;
    const int scatterBlocks = (int)((scatterThreads + 255) / 256);
    const int combBlocks = (NNODES + 127) / 128;

    // Degree counts -> inverse (once)
    cudaMemsetAsync(inv, 0, NNODES * sizeof(float), 0);
    count_kernel<<<cntBlocks, 256>>>(ei, inv);
    inv_kernel<<<(NNODES + 255) / 256, 256>>>(inv);

    // Layer 1: x -> h1 (relu)
    cudaMemsetAsync(agg, 0, aggBytes, 0);
    scatter_kernel<<<scatterBlocks, 256>>>(ei, x, agg);
    combine_kernel<128, true><<<combBlocks, 256>>>(agg, x, inv, Wl1, bl1, Wr1, h1);

    // Layer 2: h1 -> h2 (relu)
    cudaMemsetAsync(agg, 0, aggBytes, 0);
    scatter_kernel<<<scatterBlocks, 256>>>(ei, h1, agg);
    combine_kernel<128, true><<<combBlocks, 256>>>(agg, h1, inv, Wl2, bl2, Wr2, h2);

    // Layer 3: h2 -> out (no relu, COUT=64)
    cudaMemsetAsync(agg, 0, aggBytes, 0);
    scatter_kernel<<<scatterBlocks, 256>>>(ei, h2, agg);
    combine_kernel<64, false><<<combBlocks, 256>>>(agg, h2, inv, Wl3, bl3, Wr3, out);
}

// round 4
// speedup vs baseline: 1.7443x; 1.7443x over previous
#include <cuda_runtime.h>

#define NNODES 100000
#define CDIM   128
#define EDGES  3200000

// Scratch (__device__ globals; no allocation allowed)
__device__ float g_agg[(size_t)NNODES * CDIM];
__device__ float g_h1 [(size_t)NNODES * CDIM];
__device__ float g_h2 [(size_t)NNODES * CDIM];
__device__ float g_t  [(size_t)NNODES * CDIM];
__device__ float g_inv[NNODES];
__device__ int   g_deg[NNODES];
__device__ int   g_rowptr[NNODES + 1];
__device__ int   g_wcur[NNODES];
__device__ int   g_eidx[EDGES];

// ---------------------------------------------------------------------------
// CSR build step 1: degree histogram (int atomics)
__global__ void hist_kernel(const int* __restrict__ ei, int* __restrict__ deg) {
    int e = blockIdx.x * blockDim.x + threadIdx.x;
    if (e < EDGES) atomicAdd(deg + ei[EDGES + e], 1);
}

// step 2: exclusive scan over deg -> rowptr (single block, sequential chunks)
__global__ void scan_kernel(const int* __restrict__ deg, int* __restrict__ rowptr) {
    __shared__ int s[1024];
    __shared__ int carry;
    if (threadIdx.x == 0) carry = 0;
    __syncthreads();
    for (int base = 0; base < NNODES; base += 1024) {
        int i = base + threadIdx.x;
        int v = (i < NNODES) ? deg[i] : 0;
        s[threadIdx.x] = v;
        __syncthreads();
#pragma unroll
        for (int off = 1; off < 1024; off <<= 1) {
            int t = (threadIdx.x >= off) ? s[threadIdx.x - off] : 0;
            __syncthreads();
            s[threadIdx.x] += t;
            __syncthreads();
        }
        if (i < NNODES) rowptr[i] = carry + s[threadIdx.x] - v;
        __syncthreads();
        if (threadIdx.x == 1023) carry += s[1023];
        __syncthreads();
    }
    if (threadIdx.x == 0) rowptr[NNODES] = carry;
}

// step 3: init write cursors + inverse degree
__global__ void initcur_kernel(const int* __restrict__ rowptr, const int* __restrict__ deg,
                               int* __restrict__ wcur, float* __restrict__ inv) {
    int n = blockIdx.x * blockDim.x + threadIdx.x;
    if (n < NNODES) {
        wcur[n] = rowptr[n];
        inv[n]  = 1.0f / fmaxf((float)deg[n], 1.0f);
    }
}

// step 4: fill CSR adjacency (store src node ids)
__global__ void fill_kernel(const int* __restrict__ ei, int* __restrict__ wcur,
                            int* __restrict__ eidx) {
    int e = blockIdx.x * blockDim.x + threadIdx.x;
    if (e < EDGES) {
        int src = ei[e];
        int dst = ei[EDGES + e];
        int pos = atomicAdd(wcur + dst, 1);
        eidx[pos] = src;
    }
}

// ---------------------------------------------------------------------------
// Gather-aggregate: warp per node, mean of h[src] rows. W floats wide,
// source rows have stride SSTRIDE, output rows stride = W. No atomics.
template<int W, int SSTRIDE>
__global__ void aggregate_kernel(const int* __restrict__ rowptr,
                                 const int* __restrict__ eidx,
                                 const float* __restrict__ h,
                                 const float* __restrict__ inv,
                                 float* __restrict__ out) {
    constexpr int VEC = W / 32;                // 4 or 2 floats per lane
    int warp = (blockIdx.x * blockDim.x + threadIdx.x) >> 5;
    int lane = threadIdx.x & 31;
    if (warp >= NNODES) return;
    int s = rowptr[warp];
    int e = rowptr[warp + 1];

    float acc[VEC];
#pragma unroll
    for (int v = 0; v < VEC; v++) acc[v] = 0.f;

    int i = s;
    for (; i + 3 < e; i += 4) {
        int s0 = eidx[i], s1 = eidx[i + 1], s2 = eidx[i + 2], s3 = eidx[i + 3];
        const float* p0 = h + (size_t)s0 * SSTRIDE + lane * VEC;
        const float* p1 = h + (size_t)s1 * SSTRIDE + lane * VEC;
        const float* p2 = h + (size_t)s2 * SSTRIDE + lane * VEC;
        const float* p3 = h + (size_t)s3 * SSTRIDE + lane * VEC;
        if (VEC == 4) {
            float4 a = *(const float4*)p0, b = *(const float4*)p1;
            float4 c = *(const float4*)p2, d = *(const float4*)p3;
            acc[0] += a.x + b.x + c.x + d.x;
            acc[1] += a.y + b.y + c.y + d.y;
            acc[2] += a.z + b.z + c.z + d.z;
            acc[3] += a.w + b.w + c.w + d.w;
        } else {
            float2 a = *(const float2*)p0, b = *(const float2*)p1;
            float2 c = *(const float2*)p2, d = *(const float2*)p3;
            acc[0] += a.x + b.x + c.x + d.x;
            acc[1] += a.y + b.y + c.y + d.y;
        }
    }
    for (; i < e; i++) {
        const float* p = h + (size_t)eidx[i] * SSTRIDE + lane * VEC;
        if (VEC == 4) {
            float4 a = *(const float4*)p;
            acc[0] += a.x; acc[1] += a.y; acc[2] += a.z; acc[3] += a.w;
        } else {
            float2 a = *(const float2*)p;
            acc[0] += a.x; acc[1] += a.y;
        }
    }

    float iv = inv[warp];
    float* op = out + (size_t)warp * W + lane * VEC;
    if (VEC == 4) {
        float4 r = make_float4(acc[0] * iv, acc[1] * iv, acc[2] * iv, acc[3] * iv);
        *(float4*)op = r;
    } else {
        float2 r = make_float2(acc[0] * iv, acc[1] * iv);
        *(float2*)op = r;
    }
}

// ---------------------------------------------------------------------------
// Fused combine: out[n,c] = act( mean[n,:]@Wl[c,:] + bl[c] + h[n,:]@Wr[c,:] )
// (mean already scaled). Register-blocked SGEMM over implicit concat K=256.
template<int COUT, bool RELU>
__global__ __launch_bounds__(256)
void combine_kernel(const float* __restrict__ mean, const float* __restrict__ h,
                    const float* __restrict__ Wl, const float* __restrict__ bl,
                    const float* __restrict__ Wr, float* __restrict__ out) {
    constexpr int BM = 128, BK = 16;
    constexpr int TM = 8, TN = COUT / 16;

    __shared__ float As[BK][BM];
    __shared__ float Bs[BK][COUT];

    const int tid = threadIdx.x;
    const int m0  = blockIdx.x * BM;
    const int tm  = (tid >> 4) * TM;
    const int tc  = (tid & 15) * TN;

    float acc[TM][TN];
#pragma unroll
    for (int i = 0; i < TM; i++)
#pragma unroll
        for (int j = 0; j < TN; j++) acc[i][j] = 0.f;

#pragma unroll
    for (int phase = 0; phase < 2; phase++) {
        const float* Asrc = phase ? h  : mean;
        const float* Bsrc = phase ? Wr : Wl;

        for (int kc = 0; kc < CDIM; kc += BK) {
            __syncthreads();
#pragma unroll
            for (int s = tid; s < BM * BK / 4; s += 256) {
                int m  = s >> 2;
                int kg = (s & 3) * 4;
                int node = m0 + m;
                float4 v = make_float4(0.f, 0.f, 0.f, 0.f);
                if (node < NNODES)
                    v = *(const float4*)(Asrc + (size_t)node * CDIM + kc + kg);
                As[kg + 0][m] = v.x; As[kg + 1][m] = v.y;
                As[kg + 2][m] = v.z; As[kg + 3][m] = v.w;
            }
#pragma unroll
            for (int s = tid; s < COUT * BK / 4; s += 256) {
                int c  = s >> 2;
                int kg = (s & 3) * 4;
                float4 v = *(const float4*)(Bsrc + (size_t)c * CDIM + kc + kg);
                Bs[kg + 0][c] = v.x; Bs[kg + 1][c] = v.y;
                Bs[kg + 2][c] = v.z; Bs[kg + 3][c] = v.w;
            }
            __syncthreads();

#pragma unroll
            for (int k = 0; k < BK; k++) {
                float ra[TM], rb[TN];
#pragma unroll
                for (int i = 0; i < TM; i++) ra[i] = As[k][tm + i];
#pragma unroll
                for (int j = 0; j < TN; j++) rb[j] = Bs[k][tc + j];
#pragma unroll
                for (int i = 0; i < TM; i++)
#pragma unroll
                    for (int j = 0; j < TN; j++)
                        acc[i][j] += ra[i] * rb[j];
            }
        }
    }

#pragma unroll
    for (int i = 0; i < TM; i++) {
        int node = m0 + tm + i;
        if (node >= NNODES) continue;
#pragma unroll
        for (int j = 0; j < TN; j++) {
            float v = acc[i][j] + bl[tc + j];
            if (RELU) v = fmaxf(v, 0.f);
            out[(size_t)node * COUT + tc + j] = v;
        }
    }
}

// ---------------------------------------------------------------------------
// Layer-3 pre-projection: t[n, 0:64] = h2@Wl3^T, t[n, 64:128] = h2@Wr3^T
__global__ __launch_bounds__(256)
void proj_kernel(const float* __restrict__ h,
                 const float* __restrict__ Wl, const float* __restrict__ Wr,
                 float* __restrict__ t) {
    constexpr int BM = 128, BK = 16, COUT = 128;
    constexpr int TM = 8, TN = 8;

    __shared__ float As[BK][BM];
    __shared__ float Bs[BK][COUT];

    const int tid = threadIdx.x;
    const int m0  = blockIdx.x * BM;
    const int tm  = (tid >> 4) * TM;
    const int tc  = (tid & 15) * TN;

    float acc[TM][TN];
#pragma unroll
    for (int i = 0; i < TM; i++)
#pragma unroll
        for (int j = 0; j < TN; j++) acc[i][j] = 0.f;

    for (int kc = 0; kc < CDIM; kc += BK) {
        __syncthreads();
#pragma unroll
        for (int s = tid; s < BM * BK / 4; s += 256) {
            int m  = s >> 2;
            int kg = (s & 3) * 4;
            int node = m0 + m;
            float4 v = make_float4(0.f, 0.f, 0.f, 0.f);
            if (node < NNODES)
                v = *(const float4*)(h + (size_t)node * CDIM + kc + kg);
            As[kg + 0][m] = v.x; As[kg + 1][m] = v.y;
            As[kg + 2][m] = v.z; As[kg + 3][m] = v.w;
        }
#pragma unroll
        for (int s = tid; s < COUT * BK / 4; s += 256) {
            int c  = s >> 2;
            int kg = (s & 3) * 4;
            const float* w = (c < 64) ? (Wl + (size_t)c * CDIM)
                                      : (Wr + (size_t)(c - 64) * CDIM);
            float4 v = *(const float4*)(w + kc + kg);
            Bs[kg + 0][c] = v.x; Bs[kg + 1][c] = v.y;
            Bs[kg + 2][c] = v.z; Bs[kg + 3][c] = v.w;
        }
        __syncthreads();

#pragma unroll
        for (int k = 0; k < BK; k++) {
            float ra[TM], rb[TN];
#pragma unroll
            for (int i = 0; i < TM; i++) ra[i] = As[k][tm + i];
#pragma unroll
            for (int j = 0; j < TN; j++) rb[j] = Bs[k][tc + j];
#pragma unroll
            for (int i = 0; i < TM; i++)
#pragma unroll
                for (int j = 0; j < TN; j++)
                    acc[i][j] += ra[i] * rb[j];
        }
    }

#pragma unroll
    for (int i = 0; i < TM; i++) {
        int node = m0 + tm + i;
        if (node >= NNODES) continue;
#pragma unroll
        for (int j = 0; j < TN; j++)
            t[(size_t)node * COUT + tc + j] = acc[i][j];
    }
}

// Final: out[n,c] = mean_p[n,c] + t[n,64+c] + bl3[c]   (c in [0,64))
__global__ void final_kernel(const float* __restrict__ meanp,
                             const float* __restrict__ t,
                             const float* __restrict__ bl,
                             float* __restrict__ out) {
    int idx = blockIdx.x * blockDim.x + threadIdx.x;   // float4 granularity
    int total = NNODES * 16;                            // 64/4 per node
    if (idx >= total) return;
    int n  = idx >> 4;
    int c4 = (idx & 15) * 4;
    float4 a = *(const float4*)(meanp + (size_t)n * 64 + c4);
    float4 b = *(const float4*)(t + (size_t)n * CDIM + 64 + c4);
    float4 bb = *(const float4*)(bl + c4);
    float4 r = make_float4(a.x + b.x + bb.x, a.y + b.y + bb.y,
                           a.z + b.z + bb.z, a.w + b.w + bb.w);
    *(float4*)(out + (size_t)n * 64 + c4) = r;
}

// ---------------------------------------------------------------------------
extern "C" void kernel_launch(void* const* d_in, const int* in_sizes, int n_in,
                              void* d_out, int out_size) {
    const float* x   = (const float*)d_in[0];
    const int*   ei  = (const int*)d_in[1];      // int32 (JAX x64 disabled)
    const float* Wl1 = (const float*)d_in[2];
    const float* bl1 = (const float*)d_in[3];
    const float* Wr1 = (const float*)d_in[4];
    const float* Wl2 = (const float*)d_in[5];
    const float* bl2 = (const float*)d_in[6];
    const float* Wr2 = (const float*)d_in[7];
    const float* Wl3 = (const float*)d_in[8];
    const float* bl3 = (const float*)d_in[9];
    const float* Wr3 = (const float*)d_in[10];
    float* out = (float*)d_out;

    float *agg, *h1, *h2, *t, *inv;
    int *deg, *rowptr, *wcur, *eidx;
    cudaGetSymbolAddress((void**)&agg, g_agg);
    cudaGetSymbolAddress((void**)&h1,  g_h1);
    cudaGetSymbolAddress((void**)&h2,  g_h2);
    cudaGetSymbolAddress((void**)&t,   g_t);
    cudaGetSymbolAddress((void**)&inv, g_inv);
    cudaGetSymbolAddress((void**)&deg, g_deg);
    cudaGetSymbolAddress((void**)&rowptr, g_rowptr);
    cudaGetSymbolAddress((void**)&wcur, g_wcur);
    cudaGetSymbolAddress((void**)&eidx, g_eidx);

    const int eBlocks = (EDGES + 255) / 256;
    const int nBlocks = (NNODES + 255) / 256;
    const int aggBlocks = (NNODES * 32 + 255) / 256;   // warp per node
    const int combBlocks = (NNODES + 127) / 128;

    // --- CSR build (once per launch) ---
    cudaMemsetAsync(deg, 0, NNODES * sizeof(int), 0);
    hist_kernel<<<eBlocks, 256>>>(ei, deg);
    scan_kernel<<<1, 1024>>>(deg, rowptr);
    initcur_kernel<<<nBlocks, 256>>>(rowptr, deg, wcur, inv);
    fill_kernel<<<eBlocks, 256>>>(ei, wcur, eidx);

    // --- Layer 1: x -> h1 (relu) ---
    aggregate_kernel<128, 128><<<aggBlocks, 256>>>(rowptr, eidx, x, inv, agg);
    combine_kernel<128, true><<<combBlocks, 256>>>(agg, x, Wl1, bl1, Wr1, h1);

    // --- Layer 2: h1 -> h2 (relu) ---
    aggregate_kernel<128, 128><<<aggBlocks, 256>>>(rowptr, eidx, h1, inv, agg);
    combine_kernel<128, true><<<combBlocks, 256>>>(agg, h1, Wl2, bl2, Wr2, h2);

    // --- Layer 3 (pre-projected): t = h2@[Wl3;Wr3]^T, aggregate 64-wide ---
    proj_kernel<<<combBlocks, 256>>>(h2, Wl3, Wr3, t);
    aggregate_kernel<64, 128><<<aggBlocks, 256>>>(rowptr, eidx, t, inv, agg);
    final_kernel<<<(NNODES * 16 + 255) / 256, 256>>>(agg, t, bl3, out);
}

// round 6
// speedup vs baseline: 2.2630x; 1.2974x over previous
#include <cuda_runtime.h>

#define NNODES 100000
#define CDIM   128
#define EDGES  3200000
#define NB_SCAN 391   // ceil(NNODES/256)

// Scratch (__device__ globals; no allocation allowed)
__device__ float g_agg[(size_t)NNODES * CDIM];
__device__ float g_h1 [(size_t)NNODES * CDIM];
__device__ float g_h2 [(size_t)NNODES * CDIM];
__device__ float g_t  [(size_t)NNODES * CDIM];
__device__ float g_inv[NNODES];
__device__ int   g_deg[NNODES];
__device__ int   g_rowptr[NNODES + 1];
__device__ int   g_wcur[NNODES];
__device__ int   g_eidx[EDGES];
__device__ int   g_bsum[NB_SCAN];

// ---------------------------------------------------------------------------
// packed fp32x2 FMA: d = a*b + d   (FFMA2 — only reachable via PTX)
// NOTE: tied operand referenced as %0 twice (naming it %3 ICEs nvcc codegen).
__device__ __forceinline__ void ffma2(unsigned long long& d,
                                      unsigned long long a,
                                      unsigned long long b) {
    asm("fma.rn.f32x2 %0, %1, %2, %0;" : "+l"(d) : "l"(a), "l"(b));
}
__device__ __forceinline__ unsigned long long pack2(float v) {
    unsigned long long r;
    asm("mov.b64 %0, {%1, %1};" : "=l"(r) : "f"(v));
    return r;
}
union F2U { unsigned long long u; float2 f; };

// ---------------------------------------------------------------------------
// CSR build step 1: degree histogram
__global__ void hist_kernel(const int* __restrict__ ei, int* __restrict__ deg) {
    int e = blockIdx.x * blockDim.x + threadIdx.x;
    if (e < EDGES) atomicAdd(deg + ei[EDGES + e], 1);
}

// step 2a: per-256-chunk partial sums
__global__ void partial_kernel(const int* __restrict__ deg, int* __restrict__ bsum) {
    int i = blockIdx.x * 256 + threadIdx.x;
    int v = (i < NNODES) ? deg[i] : 0;
#pragma unroll
    for (int off = 16; off > 0; off >>= 1)
        v += __shfl_down_sync(0xffffffffu, v, off);
    __shared__ int ws[8];
    int wid = threadIdx.x >> 5, lane = threadIdx.x & 31;
    if (lane == 0) ws[wid] = v;
    __syncthreads();
    if (wid == 0 && lane < 8) {
        int s = ws[lane];
#pragma unroll
        for (int off = 4; off > 0; off >>= 1)
            s += __shfl_down_sync(0x000000ffu, s, off);
        if (lane == 0) bsum[blockIdx.x] = s;
    }
}

// step 2b: exclusive scan of NB_SCAN block sums (single block, 512 threads)
__global__ void scanb_kernel(int* __restrict__ bsum) {
    int t = threadIdx.x;
    int v = (t < NB_SCAN) ? bsum[t] : 0;
    int x = v;
#pragma unroll
    for (int off = 1; off < 32; off <<= 1) {
        int y = __shfl_up_sync(0xffffffffu, x, off);
        if ((t & 31) >= off) x += y;
    }
    __shared__ int ws[16];
    int wid = t >> 5, lane = t & 31;
    if (lane == 31) ws[wid] = x;
    __syncthreads();
    if (wid == 0 && lane < 16) {
        int s = ws[lane];
#pragma unroll
        for (int off = 1; off < 16; off <<= 1) {
            int y = __shfl_up_sync(0x0000ffffu, s, off);
            if (lane >= off) s += y;
        }
        ws[lane] = s;
    }
    __syncthreads();
    int woff = (wid > 0) ? ws[wid - 1] : 0;
    if (t < NB_SCAN) bsum[t] = woff + x - v;   // exclusive
}

// step 2c: re-scan chunks with offsets -> rowptr
__global__ void rescan_kernel(const int* __restrict__ deg, const int* __restrict__ bsum,
                              int* __restrict__ rowptr) {
    int i = blockIdx.x * 256 + threadIdx.x;
    int v = (i < NNODES) ? deg[i] : 0;
    int x = v;
#pragma unroll
    for (int off = 1; off < 32; off <<= 1) {
        int y = __shfl_up_sync(0xffffffffu, x, off);
        if ((threadIdx.x & 31) >= off) x += y;
    }
    __shared__ int ws[8];
    int wid = threadIdx.x >> 5, lane = threadIdx.x & 31;
    if (lane == 31) ws[wid] = x;
    __syncthreads();
    if (wid == 0 && lane < 8) {
        int s = ws[lane];
#pragma unroll
        for (int off = 1; off < 8; off <<= 1) {
            int y = __shfl_up_sync(0x000000ffu, s, off);
            if (lane >= off) s += y;
        }
        ws[lane] = s;
    }
    __syncthreads();
    int woff = (wid > 0) ? ws[wid - 1] : 0;
    if (i < NNODES) rowptr[i] = bsum[blockIdx.x] + woff + x - v;
}

// step 3: init write cursors + inverse degree (+ rowptr[NNODES]=EDGES)
__global__ void initcur_kernel(const int* __restrict__ rowptr, const int* __restrict__ deg,
                               int* __restrict__ wcur, float* __restrict__ inv,
                               int* __restrict__ rowptr_end) {
    int n = blockIdx.x * blockDim.x + threadIdx.x;
    if (n == 0) *rowptr_end = EDGES;
    if (n < NNODES) {
        wcur[n] = rowptr[n];
        inv[n]  = 1.0f / fmaxf((float)deg[n], 1.0f);
    }
}

// step 4: fill CSR adjacency
__global__ void fill_kernel(const int* __restrict__ ei, int* __restrict__ wcur,
                            int* __restrict__ eidx) {
    int e = blockIdx.x * blockDim.x + threadIdx.x;
    if (e < EDGES) {
        int src = ei[e];
        int dst = ei[EDGES + e];
        int pos = atomicAdd(wcur + dst, 1);
        eidx[pos] = src;
    }
}

// ---------------------------------------------------------------------------
// Gather-aggregate: warp per node, mean of h[src] rows. No atomics.
template<int W, int SSTRIDE>
__global__ void aggregate_kernel(const int* __restrict__ rowptr,
                                 const int* __restrict__ eidx,
                                 const float* __restrict__ h,
                                 const float* __restrict__ inv,
                                 float* __restrict__ out) {
    constexpr int VEC = W / 32;
    int warp = (blockIdx.x * blockDim.x + threadIdx.x) >> 5;
    int lane = threadIdx.x & 31;
    if (warp >= NNODES) return;
    int s = rowptr[warp];
    int e = rowptr[warp + 1];

    float acc[VEC];
#pragma unroll
    for (int v = 0; v < VEC; v++) acc[v] = 0.f;

    int i = s;
    for (; i + 3 < e; i += 4) {
        int s0 = eidx[i], s1 = eidx[i + 1], s2 = eidx[i + 2], s3 = eidx[i + 3];
        const float* p0 = h + (size_t)s0 * SSTRIDE + lane * VEC;
        const float* p1 = h + (size_t)s1 * SSTRIDE + lane * VEC;
        const float* p2 = h + (size_t)s2 * SSTRIDE + lane * VEC;
        const float* p3 = h + (size_t)s3 * SSTRIDE + lane * VEC;
        if (VEC == 4) {
            float4 a = *(const float4*)p0, b = *(const float4*)p1;
            float4 c = *(const float4*)p2, d = *(const float4*)p3;
            acc[0] += a.x + b.x + c.x + d.x;
            acc[1] += a.y + b.y + c.y + d.y;
            acc[2] += a.z + b.z + c.z + d.z;
            acc[3] += a.w + b.w + c.w + d.w;
        } else {
            float2 a = *(const float2*)p0, b = *(const float2*)p1;
            float2 c = *(const float2*)p2, d = *(const float2*)p3;
            acc[0] += a.x + b.x + c.x + d.x;
            acc[1] += a.y + b.y + c.y + d.y;
        }
    }
    for (; i < e; i++) {
        const float* p = h + (size_t)eidx[i] * SSTRIDE + lane * VEC;
        if (VEC == 4) {
            float4 a = *(const float4*)p;
            acc[0] += a.x; acc[1] += a.y; acc[2] += a.z; acc[3] += a.w;
        } else {
            float2 a = *(const float2*)p;
            acc[0] += a.x; acc[1] += a.y;
        }
    }

    float iv = inv[warp];
    float* op = out + (size_t)warp * W + lane * VEC;
    if (VEC == 4) {
        *(float4*)op = make_float4(acc[0]*iv, acc[1]*iv, acc[2]*iv, acc[3]*iv);
    } else {
        *(float2*)op = make_float2(acc[0]*iv, acc[1]*iv);
    }
}

// ---------------------------------------------------------------------------
// FFMA2 combine: out[n,c] = act( mean@Wl^T + bl + h@Wr^T )
// BM=128, BK=16, 256 threads. Per thread: 4 m-pairs (TM=8) x TN cols,
// columns strided by 16 (conflict-free B reads).
template<int COUT, bool RELU>
__global__ __launch_bounds__(256)
void combine_kernel(const float* __restrict__ mean, const float* __restrict__ h,
                    const float* __restrict__ Wl, const float* __restrict__ bl,
                    const float* __restrict__ Wr, float* __restrict__ out) {
    constexpr int BM = 128, BK = 16;
    constexpr int TN = COUT / 16;

    __shared__ float As[BK][BM + 2];
    __shared__ float Bs[BK][COUT + 2];

    const int tid = threadIdx.x;
    const int m0  = blockIdx.x * BM;
    const int tm  = (tid >> 4) * 8;    // 8 rows = 4 pairs
    const int tc0 = (tid & 15);        // cols tc0 + 16j

    unsigned long long acc[4][TN];
#pragma unroll
    for (int i = 0; i < 4; i++)
#pragma unroll
        for (int j = 0; j < TN; j++) acc[i][j] = 0ull;

#pragma unroll
    for (int phase = 0; phase < 2; phase++) {
        const float* Asrc = phase ? h  : mean;
        const float* Bsrc = phase ? Wr : Wl;

        for (int kc = 0; kc < CDIM; kc += BK) {
            __syncthreads();
#pragma unroll
            for (int s = tid; s < BM * BK / 4; s += 256) {
                int m  = s >> 2;
                int kg = (s & 3) * 4;
                int node = m0 + m;
                float4 v = make_float4(0.f, 0.f, 0.f, 0.f);
                if (node < NNODES)
                    v = *(const float4*)(Asrc + (size_t)node * CDIM + kc + kg);
                As[kg + 0][m] = v.x; As[kg + 1][m] = v.y;
                As[kg + 2][m] = v.z; As[kg + 3][m] = v.w;
            }
#pragma unroll
            for (int s = tid; s < COUT * BK / 4; s += 256) {
                int c  = s >> 2;
                int kg = (s & 3) * 4;
                float4 v = *(const float4*)(Bsrc + (size_t)c * CDIM + kc + kg);
                Bs[kg + 0][c] = v.x; Bs[kg + 1][c] = v.y;
                Bs[kg + 2][c] = v.z; Bs[kg + 3][c] = v.w;
            }
            __syncthreads();

#pragma unroll
            for (int k = 0; k < BK; k++) {
                F2U ap[4];
#pragma unroll
                for (int i = 0; i < 4; i++)
                    ap[i].f = *(const float2*)&As[k][tm + 2 * i];
                unsigned long long bp[TN];
#pragma unroll
                for (int j = 0; j < TN; j++)
                    bp[j] = pack2(Bs[k][tc0 + 16 * j]);
#pragma unroll
                for (int i = 0; i < 4; i++)
#pragma unroll
                    for (int j = 0; j < TN; j++)
                        ffma2(acc[i][j], ap[i].u, bp[j]);
            }
        }
    }

#pragma unroll
    for (int i = 0; i < 4; i++) {
        int n0 = m0 + tm + 2 * i;
#pragma unroll
        for (int j = 0; j < TN; j++) {
            int c = tc0 + 16 * j;
            F2U r; r.u = acc[i][j];
            float v0 = r.f.x + bl[c];
            float v1 = r.f.y + bl[c];
            if (RELU) { v0 = fmaxf(v0, 0.f); v1 = fmaxf(v1, 0.f); }
            if (n0 < NNODES)     out[(size_t)n0 * COUT + c]       = v0;
            if (n0 + 1 < NNODES) out[(size_t)(n0 + 1) * COUT + c] = v1;
        }
    }
}

// ---------------------------------------------------------------------------
// Layer-3 pre-projection (FFMA2): t[n,0:64]=h@Wl3^T, t[n,64:128]=h@Wr3^T
__global__ __launch_bounds__(256)
void proj_kernel(const float* __restrict__ h,
                 const float* __restrict__ Wl, const float* __restrict__ Wr,
                 float* __restrict__ t) {
    constexpr int BM = 128, BK = 16, COUT = 128, TN = 8;

    __shared__ float As[BK][BM + 2];
    __shared__ float Bs[BK][COUT + 2];

    const int tid = threadIdx.x;
    const int m0  = blockIdx.x * BM;
    const int tm  = (tid >> 4) * 8;
    const int tc0 = (tid & 15);

    unsigned long long acc[4][TN];
#pragma unroll
    for (int i = 0; i < 4; i++)
#pragma unroll
        for (int j = 0; j < TN; j++) acc[i][j] = 0ull;

    for (int kc = 0; kc < CDIM; kc += BK) {
        __syncthreads();
#pragma unroll
        for (int s = tid; s < BM * BK / 4; s += 256) {
            int m  = s >> 2;
            int kg = (s & 3) * 4;
            int node = m0 + m;
            float4 v = make_float4(0.f, 0.f, 0.f, 0.f);
            if (node < NNODES)
                v = *(const float4*)(h + (size_t)node * CDIM + kc + kg);
            As[kg + 0][m] = v.x; As[kg + 1][m] = v.y;
            As[kg + 2][m] = v.z; As[kg + 3][m] = v.w;
        }
#pragma unroll
        for (int s = tid; s < COUT * BK / 4; s += 256) {
            int c  = s >> 2;
            int kg = (s & 3) * 4;
            const float* w = (c < 64) ? (Wl + (size_t)c * CDIM)
                                      : (Wr + (size_t)(c - 64) * CDIM);
            float4 v = *(const float4*)(w + kc + kg);
            Bs[kg + 0][c] = v.x; Bs[kg + 1][c] = v.y;
            Bs[kg + 2][c] = v.z; Bs[kg + 3][c] = v.w;
        }
        __syncthreads();

#pragma unroll
        for (int k = 0; k < BK; k++) {
            F2U ap[4];
#pragma unroll
            for (int i = 0; i < 4; i++)
                ap[i].f = *(const float2*)&As[k][tm + 2 * i];
            unsigned long long bp[TN];
#pragma unroll
            for (int j = 0; j < TN; j++)
                bp[j] = pack2(Bs[k][tc0 + 16 * j]);
#pragma unroll
            for (int i = 0; i < 4; i++)
#pragma unroll
                for (int j = 0; j < TN; j++)
                    ffma2(acc[i][j], ap[i].u, bp[j]);
        }
    }

#pragma unroll
    for (int i = 0; i < 4; i++) {
        int n0 = m0 + tm + 2 * i;
#pragma unroll
        for (int j = 0; j < TN; j++) {
            int c = tc0 + 16 * j;
            F2U r; r.u = acc[i][j];
            if (n0 < NNODES)     t[(size_t)n0 * COUT + c]       = r.f.x;
            if (n0 + 1 < NNODES) t[(size_t)(n0 + 1) * COUT + c] = r.f.y;
        }
    }
}

// Final: out[n,c] = mean_p[n,c] + t[n,64+c] + bl3[c]
__global__ void final_kernel(const float* __restrict__ meanp,
                             const float* __restrict__ t,
                             const float* __restrict__ bl,
                             float* __restrict__ out) {
    int idx = blockIdx.x * blockDim.x + threadIdx.x;
    int total = NNODES * 16;
    if (idx >= total) return;
    int n  = idx >> 4;
    int c4 = (idx & 15) * 4;
    float4 a = *(const float4*)(meanp + (size_t)n * 64 + c4);
    float4 b = *(const float4*)(t + (size_t)n * CDIM + 64 + c4);
    float4 bb = *(const float4*)(bl + c4);
    *(float4*)(out + (size_t)n * 64 + c4) =
        make_float4(a.x + b.x + bb.x, a.y + b.y + bb.y,
                    a.z + b.z + bb.z, a.w + b.w + bb.w);
}

// ---------------------------------------------------------------------------
extern "C" void kernel_launch(void* const* d_in, const int* in_sizes, int n_in,
                              void* d_out, int out_size) {
    const float* x   = (const float*)d_in[0];
    const int*   ei  = (const int*)d_in[1];      // int32 (JAX x64 disabled)
    const float* Wl1 = (const float*)d_in[2];
    const float* bl1 = (const float*)d_in[3];
    const float* Wr1 = (const float*)d_in[4];
    const float* Wl2 = (const float*)d_in[5];
    const float* bl2 = (const float*)d_in[6];
    const float* Wr2 = (const float*)d_in[7];
    const float* Wl3 = (const float*)d_in[8];
    const float* bl3 = (const float*)d_in[9];
    const float* Wr3 = (const float*)d_in[10];
    float* out = (float*)d_out;

    float *agg, *h1, *h2, *t, *inv;
    int *deg, *rowptr, *wcur, *eidx, *bsum;
    cudaGetSymbolAddress((void**)&agg, g_agg);
    cudaGetSymbolAddress((void**)&h1,  g_h1);
    cudaGetSymbolAddress((void**)&h2,  g_h2);
    cudaGetSymbolAddress((void**)&t,   g_t);
    cudaGetSymbolAddress((void**)&inv, g_inv);
    cudaGetSymbolAddress((void**)&deg, g_deg);
    cudaGetSymbolAddress((void**)&rowptr, g_rowptr);
    cudaGetSymbolAddress((void**)&wcur, g_wcur);
    cudaGetSymbolAddress((void**)&eidx, g_eidx);
    cudaGetSymbolAddress((void**)&bsum, g_bsum);

    const int eBlocks = (EDGES + 255) / 256;
    const int aggBlocks = (NNODES * 32 + 255) / 256;   // warp per node
    const int combBlocks = (NNODES + 127) / 128;

    // --- CSR build (once per launch) ---
    cudaMemsetAsync(deg, 0, NNODES * sizeof(int), 0);
    hist_kernel<<<eBlocks, 256>>>(ei, deg);
    partial_kernel<<<NB_SCAN, 256>>>(deg, bsum);
    scanb_kernel<<<1, 512>>>(bsum);
    rescan_kernel<<<NB_SCAN, 256>>>(deg, bsum, rowptr);
    initcur_kernel<<<NB_SCAN, 256>>>(rowptr, deg, wcur, inv, rowptr + NNODES);
    fill_kernel<<<eBlocks, 256>>>(ei, wcur, eidx);

    // --- Layer 1: x -> h1 (relu) ---
    aggregate_kernel<128, 128><<<aggBlocks, 256>>>(rowptr, eidx, x, inv, agg);
    combine_kernel<128, true><<<combBlocks, 256>>>(agg, x, Wl1, bl1, Wr1, h1);

    // --- Layer 2: h1 -> h2 (relu) ---
    aggregate_kernel<128, 128><<<aggBlocks, 256>>>(rowptr, eidx, h1, inv, agg);
    combine_kernel<128, true><<<combBlocks, 256>>>(agg, h1, Wl2, bl2, Wr2, h2);

    // --- Layer 3 (pre-projected): t = h2@[Wl3;Wr3]^T, aggregate 64-wide ---
    proj_kernel<<<combBlocks, 256>>>(h2, Wl3, Wr3, t);
    aggregate_kernel<64, 128><<<aggBlocks, 256>>>(rowptr, eidx, t, inv, agg);
    final_kernel<<<(NNODES * 16 + 255) / 256, 256>>>(agg, t, bl3, out);
}

// round 7
// speedup vs baseline: 2.4085x; 1.0643x over previous
#include <cuda_runtime.h>
#include <cuda_fp16.h>

#define NNODES 100000
#define CDIM   128
#define EDGES  3200000
#define NB_SCAN 391   // ceil(NNODES/256)

// Scratch (__device__ globals; no allocation allowed)
__device__ float  g_agg[(size_t)NNODES * CDIM];
__device__ float  g_h1 [(size_t)NNODES * CDIM];
__device__ float  g_h2 [(size_t)NNODES * CDIM];
__device__ float  g_t  [(size_t)NNODES * CDIM];
__device__ __half g_hh [(size_t)NNODES * CDIM];   // fp16 mirror for gathers
__device__ float  g_inv[NNODES];
__device__ int    g_deg[NNODES];
__device__ int    g_rowptr[NNODES + 1];
__device__ int    g_wcur[NNODES];
__device__ int    g_eidx[EDGES];
__device__ int    g_bsum[NB_SCAN];

// ---------------------------------------------------------------------------
// packed fp32x2 FMA (FFMA2) — tied operand must be %0 (naming it %3 ICEs nvcc)
__device__ __forceinline__ void ffma2(unsigned long long& d,
                                      unsigned long long a,
                                      unsigned long long b) {
    asm("fma.rn.f32x2 %0, %1, %2, %0;" : "+l"(d) : "l"(a), "l"(b));
}
__device__ __forceinline__ unsigned long long pack2(float v) {
    unsigned long long r;
    asm("mov.b64 %0, {%1, %1};" : "=l"(r) : "f"(v));
    return r;
}
union F2U { unsigned long long u; float2 f; };

// ---------------------------------------------------------------------------
// CSR build step 1: degree histogram
__global__ void hist_kernel(const int* __restrict__ ei, int* __restrict__ deg) {
    int e = blockIdx.x * blockDim.x + threadIdx.x;
    if (e < EDGES) atomicAdd(deg + ei[EDGES + e], 1);
}

// step 2a: per-256-chunk partial sums
__global__ void partial_kernel(const int* __restrict__ deg, int* __restrict__ bsum) {
    int i = blockIdx.x * 256 + threadIdx.x;
    int v = (i < NNODES) ? deg[i] : 0;
#pragma unroll
    for (int off = 16; off > 0; off >>= 1)
        v += __shfl_down_sync(0xffffffffu, v, off);
    __shared__ int ws[8];
    int wid = threadIdx.x >> 5, lane = threadIdx.x & 31;
    if (lane == 0) ws[wid] = v;
    __syncthreads();
    if (wid == 0 && lane < 8) {
        int s = ws[lane];
#pragma unroll
        for (int off = 4; off > 0; off >>= 1)
            s += __shfl_down_sync(0x000000ffu, s, off);
        if (lane == 0) bsum[blockIdx.x] = s;
    }
}

// step 2b: exclusive scan of NB_SCAN block sums (single block, 512 threads)
__global__ void scanb_kernel(int* __restrict__ bsum) {
    int t = threadIdx.x;
    int v = (t < NB_SCAN) ? bsum[t] : 0;
    int x = v;
#pragma unroll
    for (int off = 1; off < 32; off <<= 1) {
        int y = __shfl_up_sync(0xffffffffu, x, off);
        if ((t & 31) >= off) x += y;
    }
    __shared__ int ws[16];
    int wid = t >> 5, lane = t & 31;
    if (lane == 31) ws[wid] = x;
    __syncthreads();
    if (wid == 0 && lane < 16) {
        int s = ws[lane];
#pragma unroll
        for (int off = 1; off < 16; off <<= 1) {
            int y = __shfl_up_sync(0x0000ffffu, s, off);
            if (lane >= off) s += y;
        }
        ws[lane] = s;
    }
    __syncthreads();
    int woff = (wid > 0) ? ws[wid - 1] : 0;
    if (t < NB_SCAN) bsum[t] = woff + x - v;   // exclusive
}

// step 2c: re-scan chunks with offsets -> rowptr
__global__ void rescan_kernel(const int* __restrict__ deg, const int* __restrict__ bsum,
                              int* __restrict__ rowptr) {
    int i = blockIdx.x * 256 + threadIdx.x;
    int v = (i < NNODES) ? deg[i] : 0;
    int x = v;
#pragma unroll
    for (int off = 1; off < 32; off <<= 1) {
        int y = __shfl_up_sync(0xffffffffu, x, off);
        if ((threadIdx.x & 31) >= off) x += y;
    }
    __shared__ int ws[8];
    int wid = threadIdx.x >> 5, lane = threadIdx.x & 31;
    if (lane == 31) ws[wid] = x;
    __syncthreads();
    if (wid == 0 && lane < 8) {
        int s = ws[lane];
#pragma unroll
        for (int off = 1; off < 8; off <<= 1) {
            int y = __shfl_up_sync(0x000000ffu, s, off);
            if (lane >= off) s += y;
        }
        ws[lane] = s;
    }
    __syncthreads();
    int woff = (wid > 0) ? ws[wid - 1] : 0;
    if (i < NNODES) rowptr[i] = bsum[blockIdx.x] + woff + x - v;
}

// step 3: init write cursors + inverse degree (+ rowptr[NNODES]=EDGES)
__global__ void initcur_kernel(const int* __restrict__ rowptr, const int* __restrict__ deg,
                               int* __restrict__ wcur, float* __restrict__ inv,
                               int* __restrict__ rowptr_end) {
    int n = blockIdx.x * blockDim.x + threadIdx.x;
    if (n == 0) *rowptr_end = EDGES;
    if (n < NNODES) {
        wcur[n] = rowptr[n];
        inv[n]  = 1.0f / fmaxf((float)deg[n], 1.0f);
    }
}

// step 4: fill CSR adjacency
__global__ void fill_kernel(const int* __restrict__ ei, int* __restrict__ wcur,
                            int* __restrict__ eidx) {
    int e = blockIdx.x * blockDim.x + threadIdx.x;
    if (e < EDGES) {
        int src = ei[e];
        int dst = ei[EDGES + e];
        int pos = atomicAdd(wcur + dst, 1);
        eidx[pos] = src;
    }
}

// ---------------------------------------------------------------------------
// fp32 -> fp16 mirror: take first W cols (of stride S) per node, pack tight.
// Each thread converts 8 elements (2x float4 -> uint4 of 4 half2).
template<int W, int S>
__global__ void tohalf_kernel(const float* __restrict__ in, __half* __restrict__ out) {
    long long i = (long long)blockIdx.x * blockDim.x + threadIdx.x;
    long long total = (long long)NNODES * W / 8;
    if (i >= total) return;
    int n = (int)(i * 8 / W);
    int c = (int)(i * 8 % W);
    const float4* p = (const float4*)(in + (size_t)n * S + c);
    float4 a = p[0], b = p[1];
    __half2 h0 = __float22half2_rn(make_float2(a.x, a.y));
    __half2 h1 = __float22half2_rn(make_float2(a.z, a.w));
    __half2 h2 = __float22half2_rn(make_float2(b.x, b.y));
    __half2 h3 = __float22half2_rn(make_float2(b.z, b.w));
    uint4 v;
    v.x = *(unsigned*)&h0; v.y = *(unsigned*)&h1;
    v.z = *(unsigned*)&h2; v.w = *(unsigned*)&h3;
    *(uint4*)(out + (size_t)n * W + c) = v;
}

// ---------------------------------------------------------------------------
// Gather-aggregate (fp16 gather, fp32 accumulate): warp per node, mean of
// hh[src] rows (W halves wide, tightly packed). Writes fp32 mean (scaled).
template<int W>
__global__ void aggregate_kernel(const int* __restrict__ rowptr,
                                 const int* __restrict__ eidx,
                                 const __half* __restrict__ hh,
                                 const float* __restrict__ inv,
                                 float* __restrict__ out) {
    constexpr int VEC = W / 32;                 // halves per lane: 4 or 2
    int warp = (blockIdx.x * blockDim.x + threadIdx.x) >> 5;
    int lane = threadIdx.x & 31;
    if (warp >= NNODES) return;
    int s = rowptr[warp];
    int e = rowptr[warp + 1];

    float acc[VEC];
#pragma unroll
    for (int v = 0; v < VEC; v++) acc[v] = 0.f;

    int i = s;
    for (; i + 3 < e; i += 4) {
        int s0 = eidx[i], s1 = eidx[i+1], s2 = eidx[i+2], s3 = eidx[i+3];
        if (VEC == 4) {
            uint2 u0 = *(const uint2*)(hh + (size_t)s0 * W + lane * 4);
            uint2 u1 = *(const uint2*)(hh + (size_t)s1 * W + lane * 4);
            uint2 u2 = *(const uint2*)(hh + (size_t)s2 * W + lane * 4);
            uint2 u3 = *(const uint2*)(hh + (size_t)s3 * W + lane * 4);
            float2 a, b;
            a = __half22float2(*(__half2*)&u0.x); acc[0] += a.x; acc[1] += a.y;
            b = __half22float2(*(__half2*)&u0.y); acc[2] += b.x; acc[3] += b.y;
            a = __half22float2(*(__half2*)&u1.x); acc[0] += a.x; acc[1] += a.y;
            b = __half22float2(*(__half2*)&u1.y); acc[2] += b.x; acc[3] += b.y;
            a = __half22float2(*(__half2*)&u2.x); acc[0] += a.x; acc[1] += a.y;
            b = __half22float2(*(__half2*)&u2.y); acc[2] += b.x; acc[3] += b.y;
            a = __half22float2(*(__half2*)&u3.x); acc[0] += a.x; acc[1] += a.y;
            b = __half22float2(*(__half2*)&u3.y); acc[2] += b.x; acc[3] += b.y;
        } else {
            unsigned u0 = *(const unsigned*)(hh + (size_t)s0 * W + lane * 2);
            unsigned u1 = *(const unsigned*)(hh + (size_t)s1 * W + lane * 2);
            unsigned u2 = *(const unsigned*)(hh + (size_t)s2 * W + lane * 2);
            unsigned u3 = *(const unsigned*)(hh + (size_t)s3 * W + lane * 2);
            float2 a;
            a = __half22float2(*(__half2*)&u0); acc[0] += a.x; acc[1] += a.y;
            a = __half22float2(*(__half2*)&u1); acc[0] += a.x; acc[1] += a.y;
            a = __half22float2(*(__half2*)&u2); acc[0] += a.x; acc[1] += a.y;
            a = __half22float2(*(__half2*)&u3); acc[0] += a.x; acc[1] += a.y;
        }
    }
    for (; i < e; i++) {
        int s0 = eidx[i];
        if (VEC == 4) {
            uint2 u0 = *(const uint2*)(hh + (size_t)s0 * W + lane * 4);
            float2 a = __half22float2(*(__half2*)&u0.x);
            float2 b = __half22float2(*(__half2*)&u0.y);
            acc[0] += a.x; acc[1] += a.y; acc[2] += b.x; acc[3] += b.y;
        } else {
            unsigned u0 = *(const unsigned*)(hh + (size_t)s0 * W + lane * 2);
            float2 a = __half22float2(*(__half2*)&u0);
            acc[0] += a.x; acc[1] += a.y;
        }
    }

    float iv = inv[warp];
    float* op = out + (size_t)warp * W + lane * VEC;
    if (VEC == 4) {
        *(float4*)op = make_float4(acc[0]*iv, acc[1]*iv, acc[2]*iv, acc[3]*iv);
    } else {
        *(float2*)op = make_float2(acc[0]*iv, acc[1]*iv);
    }
}

// Layer-3 fused aggregate: mean of t_l(fp16, 64-wide) + t[n,64+c] + bl3[c] -> out
__global__ void aggregate_final_kernel(const int* __restrict__ rowptr,
                                       const int* __restrict__ eidx,
                                       const __half* __restrict__ hh,   // 64-wide
                                       const float* __restrict__ t,     // N x 128
                                       const float* __restrict__ bl,
                                       const float* __restrict__ inv,
                                       float* __restrict__ out) {
    int warp = (blockIdx.x * blockDim.x + threadIdx.x) >> 5;
    int lane = threadIdx.x & 31;
    if (warp >= NNODES) return;
    int s = rowptr[warp];
    int e = rowptr[warp + 1];

    float a0 = 0.f, a1 = 0.f;
    int i = s;
    for (; i + 3 < e; i += 4) {
        int s0 = eidx[i], s1 = eidx[i+1], s2 = eidx[i+2], s3 = eidx[i+3];
        unsigned u0 = *(const unsigned*)(hh + (size_t)s0 * 64 + lane * 2);
        unsigned u1 = *(const unsigned*)(hh + (size_t)s1 * 64 + lane * 2);
        unsigned u2 = *(const unsigned*)(hh + (size_t)s2 * 64 + lane * 2);
        unsigned u3 = *(const unsigned*)(hh + (size_t)s3 * 64 + lane * 2);
        float2 a;
        a = __half22float2(*(__half2*)&u0); a0 += a.x; a1 += a.y;
        a = __half22float2(*(__half2*)&u1); a0 += a.x; a1 += a.y;
        a = __half22float2(*(__half2*)&u2); a0 += a.x; a1 += a.y;
        a = __half22float2(*(__half2*)&u3); a0 += a.x; a1 += a.y;
    }
    for (; i < e; i++) {
        unsigned u0 = *(const unsigned*)(hh + (size_t)eidx[i] * 64 + lane * 2);
        float2 a = __half22float2(*(__half2*)&u0);
        a0 += a.x; a1 += a.y;
    }

    float iv = inv[warp];
    float2 self = *(const float2*)(t + (size_t)warp * CDIM + 64 + lane * 2);
    float2 bb   = *(const float2*)(bl + lane * 2);
    *(float2*)(out + (size_t)warp * 64 + lane * 2) =
        make_float2(a0 * iv + self.x + bb.x, a1 * iv + self.y + bb.y);
}

// ---------------------------------------------------------------------------
// FFMA2 combine: out[n,c] = act( mean@Wl^T + bl + h@Wr^T )
template<int COUT, bool RELU>
__global__ __launch_bounds__(256)
void combine_kernel(const float* __restrict__ mean, const float* __restrict__ h,
                    const float* __restrict__ Wl, const float* __restrict__ bl,
                    const float* __restrict__ Wr, float* __restrict__ out) {
    constexpr int BM = 128, BK = 16;
    constexpr int TN = COUT / 16;

    __shared__ float As[BK][BM + 2];
    __shared__ float Bs[BK][COUT + 2];

    const int tid = threadIdx.x;
    const int m0  = blockIdx.x * BM;
    const int tm  = (tid >> 4) * 8;
    const int tc0 = (tid & 15);

    unsigned long long acc[4][TN];
#pragma unroll
    for (int i = 0; i < 4; i++)
#pragma unroll
        for (int j = 0; j < TN; j++) acc[i][j] = 0ull;

#pragma unroll
    for (int phase = 0; phase < 2; phase++) {
        const float* Asrc = phase ? h  : mean;
        const float* Bsrc = phase ? Wr : Wl;

        for (int kc = 0; kc < CDIM; kc += BK) {
            __syncthreads();
#pragma unroll
            for (int s = tid; s < BM * BK / 4; s += 256) {
                int m  = s >> 2;
                int kg = (s & 3) * 4;
                int node = m0 + m;
                float4 v = make_float4(0.f, 0.f, 0.f, 0.f);
                if (node < NNODES)
                    v = *(const float4*)(Asrc + (size_t)node * CDIM + kc + kg);
                As[kg + 0][m] = v.x; As[kg + 1][m] = v.y;
                As[kg + 2][m] = v.z; As[kg + 3][m] = v.w;
            }
#pragma unroll
            for (int s = tid; s < COUT * BK / 4; s += 256) {
                int c  = s >> 2;
                int kg = (s & 3) * 4;
                float4 v = *(const float4*)(Bsrc + (size_t)c * CDIM + kc + kg);
                Bs[kg + 0][c] = v.x; Bs[kg + 1][c] = v.y;
                Bs[kg + 2][c] = v.z; Bs[kg + 3][c] = v.w;
            }
            __syncthreads();

#pragma unroll
            for (int k = 0; k < BK; k++) {
                F2U ap[4];
#pragma unroll
                for (int i = 0; i < 4; i++)
                    ap[i].f = *(const float2*)&As[k][tm + 2 * i];
                unsigned long long bp[TN];
#pragma unroll
                for (int j = 0; j < TN; j++)
                    bp[j] = pack2(Bs[k][tc0 + 16 * j]);
#pragma unroll
                for (int i = 0; i < 4; i++)
#pragma unroll
                    for (int j = 0; j < TN; j++)
                        ffma2(acc[i][j], ap[i].u, bp[j]);
            }
        }
    }

#pragma unroll
    for (int i = 0; i < 4; i++) {
        int n0 = m0 + tm + 2 * i;
#pragma unroll
        for (int j = 0; j < TN; j++) {
            int c = tc0 + 16 * j;
            F2U r; r.u = acc[i][j];
            float v0 = r.f.x + bl[c];
            float v1 = r.f.y + bl[c];
            if (RELU) { v0 = fmaxf(v0, 0.f); v1 = fmaxf(v1, 0.f); }
            if (n0 < NNODES)     out[(size_t)n0 * COUT + c]       = v0;
            if (n0 + 1 < NNODES) out[(size_t)(n0 + 1) * COUT + c] = v1;
        }
    }
}

// ---------------------------------------------------------------------------
// Layer-3 pre-projection (FFMA2): t[n,0:64]=h@Wl3^T, t[n,64:128]=h@Wr3^T
__global__ __launch_bounds__(256)
void proj_kernel(const float* __restrict__ h,
                 const float* __restrict__ Wl, const float* __restrict__ Wr,
                 float* __restrict__ t) {
    constexpr int BM = 128, BK = 16, COUT = 128, TN = 8;

    __shared__ float As[BK][BM + 2];
    __shared__ float Bs[BK][COUT + 2];

    const int tid = threadIdx.x;
    const int m0  = blockIdx.x * BM;
    const int tm  = (tid >> 4) * 8;
    const int tc0 = (tid & 15);

    unsigned long long acc[4][TN];
#pragma unroll
    for (int i = 0; i < 4; i++)
#pragma unroll
        for (int j = 0; j < TN; j++) acc[i][j] = 0ull;

    for (int kc = 0; kc < CDIM; kc += BK) {
        __syncthreads();
#pragma unroll
        for (int s = tid; s < BM * BK / 4; s += 256) {
            int m  = s >> 2;
            int kg = (s & 3) * 4;
            int node = m0 + m;
            float4 v = make_float4(0.f, 0.f, 0.f, 0.f);
            if (node < NNODES)
                v = *(const float4*)(h + (size_t)node * CDIM + kc + kg);
            As[kg + 0][m] = v.x; As[kg + 1][m] = v.y;
            As[kg + 2][m] = v.z; As[kg + 3][m] = v.w;
        }
#pragma unroll
        for (int s = tid; s < COUT * BK / 4; s += 256) {
            int c  = s >> 2;
            int kg = (s & 3) * 4;
            const float* w = (c < 64) ? (Wl + (size_t)c * CDIM)
                                      : (Wr + (size_t)(c - 64) * CDIM);
            float4 v = *(const float4*)(w + kc + kg);
            Bs[kg + 0][c] = v.x; Bs[kg + 1][c] = v.y;
            Bs[kg + 2][c] = v.z; Bs[kg + 3][c] = v.w;
        }
        __syncthreads();

#pragma unroll
        for (int k = 0; k < BK; k++) {
            F2U ap[4];
#pragma unroll
            for (int i = 0; i < 4; i++)
                ap[i].f = *(const float2*)&As[k][tm + 2 * i];
            unsigned long long bp[TN];
#pragma unroll
            for (int j = 0; j < TN; j++)
                bp[j] = pack2(Bs[k][tc0 + 16 * j]);
#pragma unroll
            for (int i = 0; i < 4; i++)
#pragma unroll
                for (int j = 0; j < TN; j++)
                    ffma2(acc[i][j], ap[i].u, bp[j]);
        }
    }

#pragma unroll
    for (int i = 0; i < 4; i++) {
        int n0 = m0 + tm + 2 * i;
#pragma unroll
        for (int j = 0; j < TN; j++) {
            int c = tc0 + 16 * j;
            F2U r; r.u = acc[i][j];
            if (n0 < NNODES)     t[(size_t)n0 * COUT + c]       = r.f.x;
            if (n0 + 1 < NNODES) t[(size_t)(n0 + 1) * COUT + c] = r.f.y;
        }
    }
}

// ---------------------------------------------------------------------------
extern "C" void kernel_launch(void* const* d_in, const int* in_sizes, int n_in,
                              void* d_out, int out_size) {
    const float* x   = (const float*)d_in[0];
    const int*   ei  = (const int*)d_in[1];      // int32 (JAX x64 disabled)
    const float* Wl1 = (const float*)d_in[2];
    const float* bl1 = (const float*)d_in[3];
    const float* Wr1 = (const float*)d_in[4];
    const float* Wl2 = (const float*)d_in[5];
    const float* bl2 = (const float*)d_in[6];
    const float* Wr2 = (const float*)d_in[7];
    const float* Wl3 = (const float*)d_in[8];
    const float* bl3 = (const float*)d_in[9];
    const float* Wr3 = (const float*)d_in[10];
    float* out = (float*)d_out;

    float *agg, *h1, *h2, *t, *inv;
    __half* hh;
    int *deg, *rowptr, *wcur, *eidx, *bsum;
    cudaGetSymbolAddress((void**)&agg, g_agg);
    cudaGetSymbolAddress((void**)&h1,  g_h1);
    cudaGetSymbolAddress((void**)&h2,  g_h2);
    cudaGetSymbolAddress((void**)&t,   g_t);
    cudaGetSymbolAddress((void**)&hh,  g_hh);
    cudaGetSymbolAddress((void**)&inv, g_inv);
    cudaGetSymbolAddress((void**)&deg, g_deg);
    cudaGetSymbolAddress((void**)&rowptr, g_rowptr);
    cudaGetSymbolAddress((void**)&wcur, g_wcur);
    cudaGetSymbolAddress((void**)&eidx, g_eidx);
    cudaGetSymbolAddress((void**)&bsum, g_bsum);

    const int eBlocks = (EDGES + 255) / 256;
    const int aggBlocks = (NNODES * 32 + 255) / 256;   // warp per node
    const int combBlocks = (NNODES + 127) / 128;
    const int cvt128Blocks = (int)(((long long)NNODES * 128 / 8 + 255) / 256);
    const int cvt64Blocks  = (int)(((long long)NNODES * 64  / 8 + 255) / 256);

    // --- CSR build (once per launch) ---
    cudaMemsetAsync(deg, 0, NNODES * sizeof(int), 0);
    hist_kernel<<<eBlocks, 256>>>(ei, deg);
    partial_kernel<<<NB_SCAN, 256>>>(deg, bsum);
    scanb_kernel<<<1, 512>>>(bsum);
    rescan_kernel<<<NB_SCAN, 256>>>(deg, bsum, rowptr);
    initcur_kernel<<<NB_SCAN, 256>>>(rowptr, deg, wcur, inv, rowptr + NNODES);
    fill_kernel<<<eBlocks, 256>>>(ei, wcur, eidx);

    // --- Layer 1: x -> h1 (relu) ---
    tohalf_kernel<128, 128><<<cvt128Blocks, 256>>>(x, hh);
    aggregate_kernel<128><<<aggBlocks, 256>>>(rowptr, eidx, hh, inv, agg);
    combine_kernel<128, true><<<combBlocks, 256>>>(agg, x, Wl1, bl1, Wr1, h1);

    // --- Layer 2: h1 -> h2 (relu) ---
    tohalf_kernel<128, 128><<<cvt128Blocks, 256>>>(h1, hh);
    aggregate_kernel<128><<<aggBlocks, 256>>>(rowptr, eidx, hh, inv, agg);
    combine_kernel<128, true><<<combBlocks, 256>>>(agg, h1, Wl2, bl2, Wr2, h2);

    // --- Layer 3 (pre-projected): t = h2@[Wl3;Wr3]^T; aggregate 64-wide fused ---
    proj_kernel<<<combBlocks, 256>>>(h2, Wl3, Wr3, t);
    tohalf_kernel<64, 128><<<cvt64Blocks, 256>>>(t, hh);   // Wl half of t
    aggregate_final_kernel<<<aggBlocks, 256>>>(rowptr, eidx, hh, t, bl3, inv, out);
}